// round 2
// baseline (speedup 1.0000x reference)
#include <cuda_runtime.h>
#include <math.h>

#define NL 8
#define NS 192
#define ND 512
#define NF 2048
#define NB 16
#define EPSF 1e-5f

// ---------------- scratch (static device globals; no allocations) ----------------
__device__ float d_query[NL*NB*NS*ND];        // [i][b][t][e]
__device__ float d_key  [NL*NB*NS*ND];        // [i][b][s][e]
__device__ float d_sigse[NL*NS*NS];           // sigmoid(score_embed)
__device__ float d_x    [NL*512*NS];          // [i][r=2qk+branch][S]
__device__ float d_colp [NL*256*6*NS];        // per-t-tile colmax partials
__device__ float d_bn1m[NL], d_bn1r[NL];
__device__ float d_u    [NL*512*NF];          // fc2 output
__device__ float d_bn2m[NL*NF], d_bn2r[NL*NF];
__device__ float d_y    [NL*512];             // fc3 per-row output

// ---------------- precompute sigmoid(score_embed) ----------------
__global__ void k_sigse(const float* __restrict__ se){
    int idx = blockIdx.x*256 + threadIdx.x;
    if (idx < NL*NS*NS) d_sigse[idx] = 1.f/(1.f+expf(-se[idx]));
}

// ---------------- fc0 projection: out[i][b][t][e] = sum_d feat[b][i*D+d][t] * w0[i][e][d] + b0[i][e]
// grid (16 e-tiles, B, L), 128 threads. CTA computes [192 t][32 e], K=512.
__global__ void k_proj(const float* __restrict__ feat, const float* __restrict__ w0,
                       const float* __restrict__ b0, float* __restrict__ out){
    const int i = blockIdx.z, b = blockIdx.y, e0 = blockIdx.x*32;
    const int tid = threadIdx.x;
    const int tx = tid & 3, ty = tid >> 2;           // e = e0+tx*8+v, t = ty*6+u
    __shared__ float As[32][193];                    // [kk][t]
    __shared__ float Bs[32][33];                     // [ee][kk]
    float acc[6][8];
#pragma unroll
    for (int u=0;u<6;u++)
#pragma unroll
        for (int v=0;v<8;v++) acc[u][v]=0.f;
    const float* fbase = feat + (size_t)(b*(ND*NL) + i*ND)*NS;
    const float* wbase = w0   + (size_t)i*ND*ND + (size_t)e0*ND;
    for (int kc = 0; kc < ND; kc += 32){
        for (int idx = tid; idx < 32*NS; idx += 128){
            int kk = idx / NS, t = idx - kk*NS;
            As[kk][t] = fbase[(size_t)(kc+kk)*NS + t];
        }
        for (int idx = tid; idx < 32*32; idx += 128){
            int ee = idx >> 5, kk = idx & 31;
            Bs[ee][kk] = wbase[(size_t)ee*ND + kc + kk];
        }
        __syncthreads();
#pragma unroll
        for (int kk=0; kk<32; kk++){
            float a[6], bb[8];
#pragma unroll
            for (int u=0;u<6;u++) a[u]  = As[kk][ty*6+u];
#pragma unroll
            for (int v=0;v<8;v++) bb[v] = Bs[tx*8+v][kk];
#pragma unroll
            for (int u=0;u<6;u++)
#pragma unroll
                for (int v=0;v<8;v++) acc[u][v] = fmaf(a[u], bb[v], acc[u][v]);
        }
        __syncthreads();
    }
    float bias[8];
#pragma unroll
    for (int v=0;v<8;v++) bias[v] = b0[i*ND + e0 + tx*8+v];
    float* obase = out + (size_t)(i*NB+b)*NS*ND;
#pragma unroll
    for (int u=0;u<6;u++){
        int t = ty*6+u;
#pragma unroll
        for (int v=0;v<8;v++)
            obase[(size_t)t*ND + e0 + tx*8 + v] = acc[u][v] + bias[v];
    }
}

// ---------------- score GEMM + mask + max pooling
// grid (6 t-tiles, 256 qk, L), 128 threads. CTA: full s (192) x 32 t, K=512.
// rowmax (over s) written directly; colmax (over t) written as per-tile partials.
__global__ void k_score(){
    const int i = blockIdx.z, qk = blockIdx.y, tt = blockIdx.x;
    const int q = qk >> 4, k = qk & 15;
    const int t0 = tt*32;
    const int tid = threadIdx.x, tx = tid&3, ty = tid>>2;
    __shared__ float As[NS][33];                     // key  [s][kk]
    __shared__ float Bs[32][33];                     // query[t][kk]
    __shared__ float rowsm[4][32];
    float acc[6][8];
#pragma unroll
    for (int u=0;u<6;u++)
#pragma unroll
        for (int v=0;v<8;v++) acc[u][v]=0.f;
    const float* kbase = d_key   + (size_t)(i*NB+k)*NS*ND;
    const float* qbase = d_query + (size_t)(i*NB+q)*NS*ND + (size_t)t0*ND;
    for (int kc=0; kc<ND; kc+=32){
        for (int idx=tid; idx<NS*32; idx+=128){
            int s = idx>>5, kk = idx&31;
            As[s][kk] = kbase[(size_t)s*ND + kc+kk];
        }
        for (int idx=tid; idx<32*32; idx+=128){
            int ttv = idx>>5, kk = idx&31;
            Bs[ttv][kk] = qbase[(size_t)ttv*ND + kc+kk];
        }
        __syncthreads();
#pragma unroll
        for (int kk=0; kk<32; kk++){
            float a[6], bb[8];
#pragma unroll
            for (int u=0;u<6;u++) a[u]  = As[ty*6+u][kk];
#pragma unroll
            for (int v=0;v<8;v++) bb[v] = Bs[tx*8+v][kk];
#pragma unroll
            for (int u=0;u<6;u++)
#pragma unroll
                for (int v=0;v<8;v++) acc[u][v] = fmaf(a[u], bb[v], acc[u][v]);
        }
        __syncthreads();
    }
    // mask by sigmoid(score_embed)
    const float* sbase = d_sigse + (size_t)i*NS*NS;
#pragma unroll
    for (int u=0;u<6;u++){
        int s = ty*6+u;
#pragma unroll
        for (int v=0;v<8;v++){
            int t = t0 + tx*8 + v;
            acc[u][v] *= sbase[s*NS + t];
        }
    }
    // rowmax: max over s (per t). Reduce over u, then ty (warp shfl + smem across warps).
    float rmax[8];
#pragma unroll
    for (int v=0;v<8;v++){
        float m = acc[0][v];
#pragma unroll
        for (int u=1;u<6;u++) m = fmaxf(m, acc[u][v]);
        rmax[v] = m;
    }
#pragma unroll
    for (int off=4; off<32; off<<=1)
#pragma unroll
        for (int v=0;v<8;v++) rmax[v] = fmaxf(rmax[v], __shfl_xor_sync(0xffffffffu, rmax[v], off));
    const int w = tid>>5, lane = tid&31;
    if (lane < 4){
#pragma unroll
        for (int v=0;v<8;v++) rowsm[w][lane*8+v] = rmax[v];
    }
    __syncthreads();
    if (tid < 32){
        float m = fmaxf(fmaxf(rowsm[0][tid], rowsm[1][tid]), fmaxf(rowsm[2][tid], rowsm[3][tid]));
        d_x[((size_t)i*512 + 2*qk)*NS + t0 + tid] = m;
    }
    // colmax: max over this tile's 32 t (per s); partial across t-tiles.
    float cmax[6];
#pragma unroll
    for (int u=0;u<6;u++){
        float m = acc[u][0];
#pragma unroll
        for (int v=1;v<8;v++) m = fmaxf(m, acc[u][v]);
        cmax[u] = m;
    }
#pragma unroll
    for (int off=1; off<4; off<<=1)
#pragma unroll
        for (int u=0;u<6;u++) cmax[u] = fmaxf(cmax[u], __shfl_xor_sync(0xffffffffu, cmax[u], off));
    if (tx == 0){
#pragma unroll
        for (int u=0;u<6;u++){
            int s = ty*6+u;
            d_colp[((size_t)(i*256+qk)*6 + tt)*NS + s] = cmax[u];
        }
    }
}

// ---------------- merge colmax partials (6 t-tiles) into odd rows of x
__global__ void k_colmerge(){
    int idx = blockIdx.x*256 + threadIdx.x;       // NL*256*NS = 393216
    if (idx >= NL*256*NS) return;
    int s   = idx % NS;
    int iqk = idx / NS;
    int i   = iqk >> 8;
    int qk  = iqk & 255;
    const float* p = d_colp + (size_t)iqk*6*NS + s;
    float m = p[0];
#pragma unroll
    for (int j=1;j<6;j++) m = fmaxf(m, p[(size_t)j*NS]);
    d_x[((size_t)i*512 + 2*qk + 1)*NS + s] = m;
}

// ---------------- bn1 stats (whole-tensor mean/var per layer), double accum
__global__ void k_bn1(){
    const int i = blockIdx.x, tid = threadIdx.x;   // 8 blocks x 512 threads
    const float* p = d_x + (size_t)i*512*NS;
    double s=0.0, sq=0.0;
    for (int idx=tid; idx<512*NS; idx+=512){ double v = p[idx]; s+=v; sq+=v*v; }
    __shared__ double ss[512], sqs[512];
    ss[tid]=s; sqs[tid]=sq; __syncthreads();
    for (int off=256; off; off>>=1){
        if (tid<off){ ss[tid]+=ss[tid+off]; sqs[tid]+=sqs[tid+off]; }
        __syncthreads();
    }
    if (tid==0){
        double n = 512.0*NS;
        double mean = ss[0]/n;
        double var  = sqs[0]/n - mean*mean;
        d_bn1m[i] = (float)mean;
        d_bn1r[i] = (float)rsqrt(var + 1e-5);
    }
}

// ---------------- fc2: u = bn1(x) @ w2^T + b2.  grid (32 f-tiles, 8 r-tiles, L), 256 thr, CTA 64x64.
__global__ void k_fc2(const float* __restrict__ w2, const float* __restrict__ b2,
                      const float* __restrict__ g1, const float* __restrict__ b1){
    const int i = blockIdx.z, r0 = blockIdx.y*64, f0 = blockIdx.x*64;
    const int tid = threadIdx.x, tx = tid&15, ty = tid>>4;
    const float alpha = g1[i]*d_bn1r[i];
    const float beta  = b1[i] - d_bn1m[i]*alpha;
    __shared__ float Xs[64][33], Ws[64][33];
    float acc[4][4];
#pragma unroll
    for (int u=0;u<4;u++)
#pragma unroll
        for (int v=0;v<4;v++) acc[u][v]=0.f;
    const float* xbase = d_x + (size_t)(i*512 + r0)*NS;
    const float* wbase = w2  + (size_t)(i*NF + f0)*NS;
    for (int kc=0; kc<NS; kc+=32){
        for (int idx=tid; idx<64*32; idx+=256){
            int rr = idx>>5, kk = idx&31;
            Xs[rr][kk] = xbase[(size_t)rr*NS + kc+kk]*alpha + beta;
        }
        for (int idx=tid; idx<64*32; idx+=256){
            int ff = idx>>5, kk = idx&31;
            Ws[ff][kk] = wbase[(size_t)ff*NS + kc+kk];
        }
        __syncthreads();
#pragma unroll
        for (int kk=0; kk<32; kk++){
            float a[4], bb[4];
#pragma unroll
            for (int u=0;u<4;u++) a[u]  = Xs[ty*4+u][kk];
#pragma unroll
            for (int v=0;v<4;v++) bb[v] = Ws[tx*4+v][kk];
#pragma unroll
            for (int u=0;u<4;u++)
#pragma unroll
                for (int v=0;v<4;v++) acc[u][v] = fmaf(a[u], bb[v], acc[u][v]);
        }
        __syncthreads();
    }
#pragma unroll
    for (int u=0;u<4;u++){
        int r = r0 + ty*4 + u;
#pragma unroll
        for (int v=0;v<4;v++){
            int f = f0 + tx*4 + v;
            d_u[(size_t)(i*512 + r)*NF + f] = acc[u][v] + b2[i*NF + f];
        }
    }
}

// ---------------- bn2 stats (per-feature mean/var over 512 rows)
__global__ void k_bn2(){
    const int i = blockIdx.y, f0 = blockIdx.x*64;
    const int tid = threadIdx.x, fx = tid&63, rg = tid>>6;
    const float* p = d_u + (size_t)i*512*NF + f0 + fx;
    float s=0.f, sq=0.f;
    for (int r=rg; r<512; r+=4){ float v = p[(size_t)r*NF]; s+=v; sq+=v*v; }
    __shared__ float ss[256], sqs[256];
    ss[tid]=s; sqs[tid]=sq; __syncthreads();
    if (rg==0){
        float S  = ss[fx]  + ss[fx+64]  + ss[fx+128]  + ss[fx+192];
        float SQ = sqs[fx] + sqs[fx+64] + sqs[fx+128] + sqs[fx+192];
        float mean = S/512.f;
        float var  = SQ/512.f - mean*mean;
        d_bn2m[i*NF+f0+fx] = mean;
        d_bn2r[i*NF+f0+fx] = rsqrtf(var + EPSF);
    }
}

// ---------------- fc3: y[row] = relu(bn2(u[row])) . w3   (one warp per row)
__global__ void k_fc3(const float* __restrict__ g2, const float* __restrict__ bb2,
                      const float* __restrict__ w3){
    const int row  = blockIdx.x*8 + (threadIdx.x>>5);   // 512 blocks x 8 warps = 4096 rows
    const int lane = threadIdx.x & 31;
    const int i = row >> 9;
    const float* up = d_u + (size_t)row*NF;
    float s = 0.f;
    for (int f=lane; f<NF; f+=32){
        int gi = i*NF + f;
        float z = g2[gi]*(up[f]-d_bn2m[gi])*d_bn2r[gi] + bb2[gi];
        z = fmaxf(z, 0.f);
        s = fmaf(z, w3[gi], s);
    }
#pragma unroll
    for (int off=16; off; off>>=1) s += __shfl_xor_sync(0xffffffffu, s, off);
    if (lane==0) d_y[row] = s;
}

// ---------------- final: pair-sum, bn3 per layer, accumulate, labels
__global__ void k_final(const float* __restrict__ b3, const float* __restrict__ g3,
                        const float* __restrict__ bb3, const int* __restrict__ targets,
                        float* __restrict__ out, int out_size){
    const int qk = threadIdx.x;   // 256
    __shared__ double ss[256], sqs[256];
    float accum = 0.f;
    for (int i=0;i<NL;i++){
        float p = d_y[i*512 + 2*qk] + d_y[i*512 + 2*qk + 1] + 2.f*b3[i];
        ss[qk] = (double)p; sqs[qk] = (double)p*(double)p;
        __syncthreads();
        for (int off=128; off; off>>=1){
            if (qk<off){ ss[qk]+=ss[qk+off]; sqs[qk]+=sqs[qk+off]; }
            __syncthreads();
        }
        double mean = ss[0]/256.0;
        double var  = sqs[0]/256.0 - mean*mean;
        float rstd  = (float)rsqrt(var + 1e-5);
        accum += g3[i]*((p - (float)mean)*rstd) + bb3[i];
        __syncthreads();   // protect ss/sqs before next layer overwrites
    }
    out[qk] = accum;
    if (out_size >= 512){
        int qq = qk >> 4, kk = qk & 15;
        out[256 + qk] = (targets[qq]==targets[kk]) ? 1.f : 0.f;
    }
}

// ---------------- launcher ----------------
extern "C" void kernel_launch(void* const* d_in, const int* in_sizes, int n_in,
                              void* d_out, int out_size){
    const float* q_feat = (const float*)d_in[0];
    const float* g_feat = (const float*)d_in[1];
    const int*   targets= (const int*)  d_in[2];
    const float* se     = (const float*)d_in[3];
    const float* fc0w   = (const float*)d_in[4];
    const float* fc0b   = (const float*)d_in[5];
    const float* bn1g   = (const float*)d_in[6];
    const float* bn1b   = (const float*)d_in[7];
    const float* fc2w   = (const float*)d_in[8];
    const float* fc2b   = (const float*)d_in[9];
    const float* bn2g   = (const float*)d_in[10];
    const float* bn2b   = (const float*)d_in[11];
    const float* fc3w   = (const float*)d_in[12];
    const float* fc3b   = (const float*)d_in[13];
    const float* bn3g   = (const float*)d_in[14];
    const float* bn3b   = (const float*)d_in[15];
    float* out = (float*)d_out;

    float* d_query_p; cudaGetSymbolAddress((void**)&d_query_p, d_query);
    float* d_key_p;   cudaGetSymbolAddress((void**)&d_key_p,   d_key);

    k_sigse<<<(NL*NS*NS+255)/256, 256>>>(se);
    k_proj<<<dim3(16, NB, NL), 128>>>(q_feat, fc0w, fc0b, d_query_p);
    k_proj<<<dim3(16, NB, NL), 128>>>(g_feat, fc0w, fc0b, d_key_p);
    k_score<<<dim3(6, 256, NL), 128>>>();
    k_colmerge<<<(NL*256*NS+255)/256, 256>>>();
    k_bn1<<<NL, 512>>>();
    k_fc2<<<dim3(32, 8, NL), 256>>>(fc2w, fc2b, bn1g, bn1b);
    k_bn2<<<dim3(32, NL), 256>>>();
    k_fc3<<<512, 256>>>(bn2g, bn2b, fc3w);
    k_final<<<1, 256>>>(fc3b, bn3g, bn3b, targets, out, out_size);
}

// round 3
// speedup vs baseline: 1.0002x; 1.0002x over previous
#include <cuda_runtime.h>
#include <math.h>

#define NL 8
#define NS 192
#define ND 512
#define NF 2048
#define NB 16
#define EPSF 1e-5f

// ---------------- scratch (static device globals; no allocations) ----------------
__device__ float d_query[NL*NB*NS*ND];        // [i][b][t][e]
__device__ float d_key  [NL*NB*NS*ND];        // [i][b][s][e]
__device__ float d_sigse[NL*NS*NS];           // sigmoid(score_embed)
__device__ float d_x    [NL*512*NS];          // [i][r=2qk+branch][S]
__device__ float d_colp [NL*256*6*NS];        // per-t-tile colmax partials
__device__ float d_bn1m[NL], d_bn1r[NL];
__device__ float d_u    [NL*512*NF];          // fc2 output
__device__ float d_bn2m[NL*NF], d_bn2r[NL*NF];
__device__ float d_y    [NL*512];             // fc3 per-row output

// ---------------- precompute sigmoid(score_embed) ----------------
__global__ void k_sigse(const float* __restrict__ se){
    int idx = blockIdx.x*256 + threadIdx.x;
    if (idx < NL*NS*NS) d_sigse[idx] = 1.f/(1.f+expf(-se[idx]));
}

// ---------------- fc0 projection: out[i][b][t][e] = sum_d feat[b][i*D+d][t] * w0[i][e][d] + b0[i][e]
// grid (16 e-tiles, B, L), 128 threads. CTA computes [192 t][32 e], K=512.
__global__ void k_proj(const float* __restrict__ feat, const float* __restrict__ w0,
                       const float* __restrict__ b0, float* __restrict__ out){
    const int i = blockIdx.z, b = blockIdx.y, e0 = blockIdx.x*32;
    const int tid = threadIdx.x;
    const int tx = tid & 3, ty = tid >> 2;           // e = e0+tx*8+v, t = ty*6+u
    __shared__ float As[32][193];                    // [kk][t]
    __shared__ float Bs[32][33];                     // [ee][kk]
    float acc[6][8];
#pragma unroll
    for (int u=0;u<6;u++)
#pragma unroll
        for (int v=0;v<8;v++) acc[u][v]=0.f;
    const float* fbase = feat + (size_t)(b*(ND*NL) + i*ND)*NS;
    const float* wbase = w0   + (size_t)i*ND*ND + (size_t)e0*ND;
    for (int kc = 0; kc < ND; kc += 32){
        for (int idx = tid; idx < 32*NS; idx += 128){
            int kk = idx / NS, t = idx - kk*NS;
            As[kk][t] = fbase[(size_t)(kc+kk)*NS + t];
        }
        for (int idx = tid; idx < 32*32; idx += 128){
            int ee = idx >> 5, kk = idx & 31;
            Bs[ee][kk] = wbase[(size_t)ee*ND + kc + kk];
        }
        __syncthreads();
#pragma unroll
        for (int kk=0; kk<32; kk++){
            float a[6], bb[8];
#pragma unroll
            for (int u=0;u<6;u++) a[u]  = As[kk][ty*6+u];
#pragma unroll
            for (int v=0;v<8;v++) bb[v] = Bs[tx*8+v][kk];
#pragma unroll
            for (int u=0;u<6;u++)
#pragma unroll
                for (int v=0;v<8;v++) acc[u][v] = fmaf(a[u], bb[v], acc[u][v]);
        }
        __syncthreads();
    }
    float bias[8];
#pragma unroll
    for (int v=0;v<8;v++) bias[v] = b0[i*ND + e0 + tx*8+v];
    float* obase = out + (size_t)(i*NB+b)*NS*ND;
#pragma unroll
    for (int u=0;u<6;u++){
        int t = ty*6+u;
#pragma unroll
        for (int v=0;v<8;v++)
            obase[(size_t)t*ND + e0 + tx*8 + v] = acc[u][v] + bias[v];
    }
}

// ---------------- score GEMM + mask + max pooling
// grid (6 t-tiles, 256 qk, L), 128 threads. CTA: full s (192) x 32 t, K=512.
// rowmax (over s) written directly; colmax (over t) written as per-tile partials.
__global__ void k_score(){
    const int i = blockIdx.z, qk = blockIdx.y, tt = blockIdx.x;
    const int q = qk >> 4, k = qk & 15;
    const int t0 = tt*32;
    const int tid = threadIdx.x, tx = tid&3, ty = tid>>2;
    __shared__ float As[NS][33];                     // key  [s][kk]
    __shared__ float Bs[32][33];                     // query[t][kk]
    __shared__ float rowsm[4][32];
    float acc[6][8];
#pragma unroll
    for (int u=0;u<6;u++)
#pragma unroll
        for (int v=0;v<8;v++) acc[u][v]=0.f;
    const float* kbase = d_key   + (size_t)(i*NB+k)*NS*ND;
    const float* qbase = d_query + (size_t)(i*NB+q)*NS*ND + (size_t)t0*ND;
    for (int kc=0; kc<ND; kc+=32){
        for (int idx=tid; idx<NS*32; idx+=128){
            int s = idx>>5, kk = idx&31;
            As[s][kk] = kbase[(size_t)s*ND + kc+kk];
        }
        for (int idx=tid; idx<32*32; idx+=128){
            int ttv = idx>>5, kk = idx&31;
            Bs[ttv][kk] = qbase[(size_t)ttv*ND + kc+kk];
        }
        __syncthreads();
#pragma unroll
        for (int kk=0; kk<32; kk++){
            float a[6], bb[8];
#pragma unroll
            for (int u=0;u<6;u++) a[u]  = As[ty*6+u][kk];
#pragma unroll
            for (int v=0;v<8;v++) bb[v] = Bs[tx*8+v][kk];
#pragma unroll
            for (int u=0;u<6;u++)
#pragma unroll
                for (int v=0;v<8;v++) acc[u][v] = fmaf(a[u], bb[v], acc[u][v]);
        }
        __syncthreads();
    }
    // mask by sigmoid(score_embed)
    const float* sbase = d_sigse + (size_t)i*NS*NS;
#pragma unroll
    for (int u=0;u<6;u++){
        int s = ty*6+u;
#pragma unroll
        for (int v=0;v<8;v++){
            int t = t0 + tx*8 + v;
            acc[u][v] *= sbase[s*NS + t];
        }
    }
    // rowmax: max over s (per t). Reduce over u, then ty (warp shfl + smem across warps).
    float rmax[8];
#pragma unroll
    for (int v=0;v<8;v++){
        float m = acc[0][v];
#pragma unroll
        for (int u=1;u<6;u++) m = fmaxf(m, acc[u][v]);
        rmax[v] = m;
    }
#pragma unroll
    for (int off=4; off<32; off<<=1)
#pragma unroll
        for (int v=0;v<8;v++) rmax[v] = fmaxf(rmax[v], __shfl_xor_sync(0xffffffffu, rmax[v], off));
    const int w = tid>>5, lane = tid&31;
    if (lane < 4){
#pragma unroll
        for (int v=0;v<8;v++) rowsm[w][lane*8+v] = rmax[v];
    }
    __syncthreads();
    if (tid < 32){
        float m = fmaxf(fmaxf(rowsm[0][tid], rowsm[1][tid]), fmaxf(rowsm[2][tid], rowsm[3][tid]));
        d_x[((size_t)i*512 + 2*qk)*NS + t0 + tid] = m;
    }
    // colmax: max over this tile's 32 t (per s); partial across t-tiles.
    float cmax[6];
#pragma unroll
    for (int u=0;u<6;u++){
        float m = acc[u][0];
#pragma unroll
        for (int v=1;v<8;v++) m = fmaxf(m, acc[u][v]);
        cmax[u] = m;
    }
#pragma unroll
    for (int off=1; off<4; off<<=1)
#pragma unroll
        for (int u=0;u<6;u++) cmax[u] = fmaxf(cmax[u], __shfl_xor_sync(0xffffffffu, cmax[u], off));
    if (tx == 0){
#pragma unroll
        for (int u=0;u<6;u++){
            int s = ty*6+u;
            d_colp[((size_t)(i*256+qk)*6 + tt)*NS + s] = cmax[u];
        }
    }
}

// ---------------- merge colmax partials (6 t-tiles) into odd rows of x
__global__ void k_colmerge(){
    int idx = blockIdx.x*256 + threadIdx.x;       // NL*256*NS = 393216
    if (idx >= NL*256*NS) return;
    int s   = idx % NS;
    int iqk = idx / NS;
    int i   = iqk >> 8;
    int qk  = iqk & 255;
    const float* p = d_colp + (size_t)iqk*6*NS + s;
    float m = p[0];
#pragma unroll
    for (int j=1;j<6;j++) m = fmaxf(m, p[(size_t)j*NS]);
    d_x[((size_t)i*512 + 2*qk + 1)*NS + s] = m;
}

// ---------------- bn1 stats (whole-tensor mean/var per layer), double accum
__global__ void k_bn1(){
    const int i = blockIdx.x, tid = threadIdx.x;   // 8 blocks x 512 threads
    const float* p = d_x + (size_t)i*512*NS;
    double s=0.0, sq=0.0;
    for (int idx=tid; idx<512*NS; idx+=512){ double v = p[idx]; s+=v; sq+=v*v; }
    __shared__ double ss[512], sqs[512];
    ss[tid]=s; sqs[tid]=sq; __syncthreads();
    for (int off=256; off; off>>=1){
        if (tid<off){ ss[tid]+=ss[tid+off]; sqs[tid]+=sqs[tid+off]; }
        __syncthreads();
    }
    if (tid==0){
        double n = 512.0*NS;
        double mean = ss[0]/n;
        double var  = sqs[0]/n - mean*mean;
        d_bn1m[i] = (float)mean;
        d_bn1r[i] = (float)rsqrt(var + 1e-5);
    }
}

// ---------------- fc2: u = bn1(x) @ w2^T + b2.  grid (32 f-tiles, 8 r-tiles, L), 256 thr, CTA 64x64.
__global__ void k_fc2(const float* __restrict__ w2, const float* __restrict__ b2,
                      const float* __restrict__ g1, const float* __restrict__ b1){
    const int i = blockIdx.z, r0 = blockIdx.y*64, f0 = blockIdx.x*64;
    const int tid = threadIdx.x, tx = tid&15, ty = tid>>4;
    const float alpha = g1[i]*d_bn1r[i];
    const float beta  = b1[i] - d_bn1m[i]*alpha;
    __shared__ float Xs[64][33], Ws[64][33];
    float acc[4][4];
#pragma unroll
    for (int u=0;u<4;u++)
#pragma unroll
        for (int v=0;v<4;v++) acc[u][v]=0.f;
    const float* xbase = d_x + (size_t)(i*512 + r0)*NS;
    const float* wbase = w2  + (size_t)(i*NF + f0)*NS;
    for (int kc=0; kc<NS; kc+=32){
        for (int idx=tid; idx<64*32; idx+=256){
            int rr = idx>>5, kk = idx&31;
            Xs[rr][kk] = xbase[(size_t)rr*NS + kc+kk]*alpha + beta;
        }
        for (int idx=tid; idx<64*32; idx+=256){
            int ff = idx>>5, kk = idx&31;
            Ws[ff][kk] = wbase[(size_t)ff*NS + kc+kk];
        }
        __syncthreads();
#pragma unroll
        for (int kk=0; kk<32; kk++){
            float a[4], bb[4];
#pragma unroll
            for (int u=0;u<4;u++) a[u]  = Xs[ty*4+u][kk];
#pragma unroll
            for (int v=0;v<4;v++) bb[v] = Ws[tx*4+v][kk];
#pragma unroll
            for (int u=0;u<4;u++)
#pragma unroll
                for (int v=0;v<4;v++) acc[u][v] = fmaf(a[u], bb[v], acc[u][v]);
        }
        __syncthreads();
    }
#pragma unroll
    for (int u=0;u<4;u++){
        int r = r0 + ty*4 + u;
#pragma unroll
        for (int v=0;v<4;v++){
            int f = f0 + tx*4 + v;
            d_u[(size_t)(i*512 + r)*NF + f] = acc[u][v] + b2[i*NF + f];
        }
    }
}

// ---------------- bn2 stats (per-feature mean/var over 512 rows)
__global__ void k_bn2(){
    const int i = blockIdx.y, f0 = blockIdx.x*64;
    const int tid = threadIdx.x, fx = tid&63, rg = tid>>6;
    const float* p = d_u + (size_t)i*512*NF + f0 + fx;
    float s=0.f, sq=0.f;
    for (int r=rg; r<512; r+=4){ float v = p[(size_t)r*NF]; s+=v; sq+=v*v; }
    __shared__ float ss[256], sqs[256];
    ss[tid]=s; sqs[tid]=sq; __syncthreads();
    if (rg==0){
        float S  = ss[fx]  + ss[fx+64]  + ss[fx+128]  + ss[fx+192];
        float SQ = sqs[fx] + sqs[fx+64] + sqs[fx+128] + sqs[fx+192];
        float mean = S/512.f;
        float var  = SQ/512.f - mean*mean;
        d_bn2m[i*NF+f0+fx] = mean;
        d_bn2r[i*NF+f0+fx] = rsqrtf(var + EPSF);
    }
}

// ---------------- fc3: y[row] = relu(bn2(u[row])) . w3   (one warp per row)
__global__ void k_fc3(const float* __restrict__ g2, const float* __restrict__ bb2,
                      const float* __restrict__ w3){
    const int row  = blockIdx.x*8 + (threadIdx.x>>5);   // 512 blocks x 8 warps = 4096 rows
    const int lane = threadIdx.x & 31;
    const int i = row >> 9;
    const float* up = d_u + (size_t)row*NF;
    float s = 0.f;
    for (int f=lane; f<NF; f+=32){
        int gi = i*NF + f;
        float z = g2[gi]*(up[f]-d_bn2m[gi])*d_bn2r[gi] + bb2[gi];
        z = fmaxf(z, 0.f);
        s = fmaf(z, w3[gi], s);
    }
#pragma unroll
    for (int off=16; off; off>>=1) s += __shfl_xor_sync(0xffffffffu, s, off);
    if (lane==0) d_y[row] = s;
}

// ---------------- final: pair-sum, bn3 per layer, accumulate, labels
__global__ void k_final(const float* __restrict__ b3, const float* __restrict__ g3,
                        const float* __restrict__ bb3, const int* __restrict__ targets,
                        float* __restrict__ out, int out_size){
    const int qk = threadIdx.x;   // 256
    __shared__ double ss[256], sqs[256];
    float accum = 0.f;
    for (int i=0;i<NL;i++){
        float p = d_y[i*512 + 2*qk] + d_y[i*512 + 2*qk + 1] + 2.f*b3[i];
        ss[qk] = (double)p; sqs[qk] = (double)p*(double)p;
        __syncthreads();
        for (int off=128; off; off>>=1){
            if (qk<off){ ss[qk]+=ss[qk+off]; sqs[qk]+=sqs[qk+off]; }
            __syncthreads();
        }
        double mean = ss[0]/256.0;
        double var  = sqs[0]/256.0 - mean*mean;
        float rstd  = (float)rsqrt(var + 1e-5);
        accum += g3[i]*((p - (float)mean)*rstd) + bb3[i];
        __syncthreads();   // protect ss/sqs before next layer overwrites
    }
    out[qk] = accum;
    if (out_size >= 512){
        int qq = qk >> 4, kk = qk & 15;
        out[256 + qk] = (targets[qq]==targets[kk]) ? 1.f : 0.f;
    }
}

// ---------------- launcher ----------------
extern "C" void kernel_launch(void* const* d_in, const int* in_sizes, int n_in,
                              void* d_out, int out_size){
    const float* q_feat = (const float*)d_in[0];
    const float* g_feat = (const float*)d_in[1];
    const int*   targets= (const int*)  d_in[2];
    const float* se     = (const float*)d_in[3];
    const float* fc0w   = (const float*)d_in[4];
    const float* fc0b   = (const float*)d_in[5];
    const float* bn1g   = (const float*)d_in[6];
    const float* bn1b   = (const float*)d_in[7];
    const float* fc2w   = (const float*)d_in[8];
    const float* fc2b   = (const float*)d_in[9];
    const float* bn2g   = (const float*)d_in[10];
    const float* bn2b   = (const float*)d_in[11];
    const float* fc3w   = (const float*)d_in[12];
    const float* fc3b   = (const float*)d_in[13];
    const float* bn3g   = (const float*)d_in[14];
    const float* bn3b   = (const float*)d_in[15];
    float* out = (float*)d_out;

    float* d_query_p; cudaGetSymbolAddress((void**)&d_query_p, d_query);
    float* d_key_p;   cudaGetSymbolAddress((void**)&d_key_p,   d_key);

    k_sigse<<<(NL*NS*NS+255)/256, 256>>>(se);
    k_proj<<<dim3(16, NB, NL), 128>>>(q_feat, fc0w, fc0b, d_query_p);
    k_proj<<<dim3(16, NB, NL), 128>>>(g_feat, fc0w, fc0b, d_key_p);
    k_score<<<dim3(6, 256, NL), 128>>>();
    k_colmerge<<<(NL*256*NS+255)/256, 256>>>();
    k_bn1<<<NL, 512>>>();
    k_fc2<<<dim3(32, 8, NL), 256>>>(fc2w, fc2b, bn1g, bn1b);
    k_bn2<<<dim3(32, NL), 256>>>();
    k_fc3<<<512, 256>>>(bn2g, bn2b, fc3w);
    k_final<<<1, 256>>>(fc3b, bn3g, bn3b, targets, out, out_size);
}